// round 1
// baseline (speedup 1.0000x reference)
#include <cuda_runtime.h>
#include <math.h>

#define BATCH 8
#define SEQ 512
#define DIM 768
#define HEADS 12
#define HD 64
#define MROWS (BATCH*SEQ)          // 4096
#define QKV_COLS (3*DIM)           // 2304
#define BHN (BATCH*HEADS*SEQ)      // 49152
#define HEAD_ELEMS (BATCH*HEADS*SEQ*HD)   // 3145728
#define ATTN_ELEMS ((size_t)BATCH*HEADS*SEQ*SEQ) // 25165824
#define LN_EPS 1e-5f

// ---------------- scratch (static device globals; no allocation) -------------
__device__ float g_qkv[MROWS * QKV_COLS];     // 37.7 MB
__device__ float g_q2[HEAD_ELEMS];            // 12.6 MB
__device__ float g_k2[HEAD_ELEMS];
__device__ float g_v[HEAD_ELEMS];
__device__ float g_outbh[MROWS * DIM];        // (B,N,DIM) pre-proj
__device__ double g_stats[16];                // [b][0]=sum, [b][1]=sumsq
__device__ float g_meanr[16];                 // [b][0]=mean, [b][1]=rstd

// ---------------- generic NT SGEMM: C[M,N] = A[M,K] @ B[N,K]^T (+bias) -------
// 128x128 tile, BK=16, 256 threads, 8x8 per thread
__global__ __launch_bounds__(256) void gemm_nt_kernel(
    const float* __restrict__ A, const float* __restrict__ B,
    float* __restrict__ C, const float* __restrict__ bias,
    int M, int Nc, int K)
{
    __shared__ __align__(16) float As[16][128];
    __shared__ __align__(16) float Bs[16][128];
    const int tid = threadIdx.x;
    const int bm = blockIdx.y * 128;
    const int bn = blockIdx.x * 128;
    const int ty = tid >> 4, tx = tid & 15;

    float acc[8][8];
#pragma unroll
    for (int i = 0; i < 8; i++)
#pragma unroll
        for (int j = 0; j < 8; j++) acc[i][j] = 0.f;

    for (int kt = 0; kt < K; kt += 16) {
#pragma unroll
        for (int l = 0; l < 2; l++) {
            int j = tid + l * 256;          // 512 float4 per tile
            int row = j >> 2;
            int k4 = (j & 3) << 2;
            float4 va = *reinterpret_cast<const float4*>(&A[(size_t)(bm + row) * K + kt + k4]);
            As[k4 + 0][row] = va.x; As[k4 + 1][row] = va.y;
            As[k4 + 2][row] = va.z; As[k4 + 3][row] = va.w;
            float4 vb = *reinterpret_cast<const float4*>(&B[(size_t)(bn + row) * K + kt + k4]);
            Bs[k4 + 0][row] = vb.x; Bs[k4 + 1][row] = vb.y;
            Bs[k4 + 2][row] = vb.z; Bs[k4 + 3][row] = vb.w;
        }
        __syncthreads();
#pragma unroll
        for (int k = 0; k < 16; k++) {
            float a[8], b[8];
            *reinterpret_cast<float4*>(a)     = *reinterpret_cast<float4*>(&As[k][ty * 8]);
            *reinterpret_cast<float4*>(a + 4) = *reinterpret_cast<float4*>(&As[k][ty * 8 + 4]);
            *reinterpret_cast<float4*>(b)     = *reinterpret_cast<float4*>(&Bs[k][tx * 8]);
            *reinterpret_cast<float4*>(b + 4) = *reinterpret_cast<float4*>(&Bs[k][tx * 8 + 4]);
#pragma unroll
            for (int i = 0; i < 8; i++)
#pragma unroll
                for (int j = 0; j < 8; j++) acc[i][j] = fmaf(a[i], b[j], acc[i][j]);
        }
        __syncthreads();
    }

    float bb[8];
#pragma unroll
    for (int j = 0; j < 8; j++) bb[j] = bias ? bias[bn + tx * 8 + j] : 0.f;
#pragma unroll
    for (int i = 0; i < 8; i++) {
        int r = bm + ty * 8 + i;
        float4 v0 = make_float4(acc[i][0] + bb[0], acc[i][1] + bb[1], acc[i][2] + bb[2], acc[i][3] + bb[3]);
        float4 v1 = make_float4(acc[i][4] + bb[4], acc[i][5] + bb[5], acc[i][6] + bb[6], acc[i][7] + bb[7]);
        *reinterpret_cast<float4*>(&C[(size_t)r * Nc + bn + tx * 8])     = v0;
        *reinterpret_cast<float4*>(&C[(size_t)r * Nc + bn + tx * 8 + 4]) = v1;
    }
}

// --------- normalize q,k (squared-unit), repack q2/k2/v to (B,H,N,d) ---------
__global__ __launch_bounds__(64) void qkvnorm_kernel(
    const float* __restrict__ qkv, float* __restrict__ q2,
    float* __restrict__ k2, float* __restrict__ vout)
{
    int idx = blockIdx.x;                 // b*H*SEQ + h*SEQ + n
    int n = idx & (SEQ - 1);
    int h = (idx / SEQ) % HEADS;
    int b = idx / (SEQ * HEADS);
    int lane = threadIdx.x & 31, w = threadIdx.x >> 5;

    const float* row = qkv + (size_t)(b * SEQ + n) * QKV_COLS;
    const float* src = row + w * DIM + h * HD;   // w=0:q, w=1:k
    float x0 = src[lane], x1 = src[lane + 32];
    float ss = x0 * x0 + x1 * x1;
#pragma unroll
    for (int o = 16; o; o >>= 1) ss += __shfl_xor_sync(0xffffffffu, ss, o);
    float inv = 1.0f / ss;

    float* dst = (w == 0 ? q2 : k2) + ((size_t)(b * HEADS + h) * SEQ + n) * HD;
    dst[lane]      = x0 * x0 * inv;
    dst[lane + 32] = x1 * x1 * inv;

    if (w == 0) {
        const float* vs = row + 2 * DIM + h * HD;
        float* vd = vout + ((size_t)(b * HEADS + h) * SEQ + n) * HD;
        vd[lane] = vs[lane];
        vd[lane + 32] = vs[lane + 32];
    }
}

__global__ void zero_stats_kernel(double* s) { if (threadIdx.x < 16) s[threadIdx.x] = 0.0; }

// ---- attn_raw = q2 @ k2^T per (b,h), K=64; accumulate LN stats (fp64) -------
__global__ __launch_bounds__(256) void attn_gemm_kernel(
    const float* __restrict__ q2, const float* __restrict__ k2,
    float* __restrict__ attn, double* __restrict__ stats)
{
    __shared__ __align__(16) float As[16][128];
    __shared__ __align__(16) float Bs[16][128];
    const int bh = blockIdx.z;
    const int b = bh / HEADS;
    const float* A = q2 + (size_t)bh * SEQ * HD;
    const float* B = k2 + (size_t)bh * SEQ * HD;
    float* Cp = attn + (size_t)bh * SEQ * SEQ;
    const int tid = threadIdx.x;
    const int bm = blockIdx.y * 128;
    const int bn = blockIdx.x * 128;
    const int ty = tid >> 4, tx = tid & 15;

    float acc[8][8];
#pragma unroll
    for (int i = 0; i < 8; i++)
#pragma unroll
        for (int j = 0; j < 8; j++) acc[i][j] = 0.f;

    for (int kt = 0; kt < HD; kt += 16) {
#pragma unroll
        for (int l = 0; l < 2; l++) {
            int j = tid + l * 256;
            int row = j >> 2;
            int k4 = (j & 3) << 2;
            float4 va = *reinterpret_cast<const float4*>(&A[(size_t)(bm + row) * HD + kt + k4]);
            As[k4 + 0][row] = va.x; As[k4 + 1][row] = va.y;
            As[k4 + 2][row] = va.z; As[k4 + 3][row] = va.w;
            float4 vb = *reinterpret_cast<const float4*>(&B[(size_t)(bn + row) * HD + kt + k4]);
            Bs[k4 + 0][row] = vb.x; Bs[k4 + 1][row] = vb.y;
            Bs[k4 + 2][row] = vb.z; Bs[k4 + 3][row] = vb.w;
        }
        __syncthreads();
#pragma unroll
        for (int k = 0; k < 16; k++) {
            float a[8], bv[8];
            *reinterpret_cast<float4*>(a)      = *reinterpret_cast<float4*>(&As[k][ty * 8]);
            *reinterpret_cast<float4*>(a + 4)  = *reinterpret_cast<float4*>(&As[k][ty * 8 + 4]);
            *reinterpret_cast<float4*>(bv)     = *reinterpret_cast<float4*>(&Bs[k][tx * 8]);
            *reinterpret_cast<float4*>(bv + 4) = *reinterpret_cast<float4*>(&Bs[k][tx * 8 + 4]);
#pragma unroll
            for (int i = 0; i < 8; i++)
#pragma unroll
                for (int j = 0; j < 8; j++) acc[i][j] = fmaf(a[i], bv[j], acc[i][j]);
        }
        __syncthreads();
    }

    double s1 = 0.0, s2 = 0.0;
#pragma unroll
    for (int i = 0; i < 8; i++) {
        int r = bm + ty * 8 + i;
        float4 v0 = make_float4(acc[i][0], acc[i][1], acc[i][2], acc[i][3]);
        float4 v1 = make_float4(acc[i][4], acc[i][5], acc[i][6], acc[i][7]);
        *reinterpret_cast<float4*>(&Cp[(size_t)r * SEQ + bn + tx * 8])     = v0;
        *reinterpret_cast<float4*>(&Cp[(size_t)r * SEQ + bn + tx * 8 + 4]) = v1;
#pragma unroll
        for (int j = 0; j < 8; j++) {
            double v = (double)acc[i][j];
            s1 += v; s2 += v * v;
        }
    }
#pragma unroll
    for (int o = 16; o; o >>= 1) {
        s1 += __shfl_xor_sync(0xffffffffu, s1, o);
        s2 += __shfl_xor_sync(0xffffffffu, s2, o);
    }
    __shared__ double sh1[8], sh2[8];
    int wid = tid >> 5, lane = tid & 31;
    if (lane == 0) { sh1[wid] = s1; sh2[wid] = s2; }
    __syncthreads();
    if (tid == 0) {
        double t1 = 0.0, t2 = 0.0;
#pragma unroll
        for (int i = 0; i < 8; i++) { t1 += sh1[i]; t2 += sh2[i]; }
        atomicAdd(&stats[b * 2], t1);
        atomicAdd(&stats[b * 2 + 1], t2);
    }
}

__global__ void finalize_stats_kernel(const double* __restrict__ s, float* __restrict__ mr)
{
    int b = threadIdx.x;
    if (b < BATCH) {
        double cnt = (double)HEADS * SEQ * SEQ;
        double mean = s[b * 2] / cnt;
        double var = s[b * 2 + 1] / cnt - mean * mean;
        mr[b * 2] = (float)mean;
        mr[b * 2 + 1] = (float)(1.0 / sqrt(var + (double)LN_EPS));
    }
}

// ---- fused: normalize attn in place (writes 2nd output) + out = attn_n @ v --
// per (b,h): C(512x64) over row-tiles of 128; BK=16; 256 threads; 8x4/thread
__global__ __launch_bounds__(256) void norm_attnv_kernel(
    float* __restrict__ attn, const float* __restrict__ lnw,
    const float* __restrict__ lnb, const float* __restrict__ v,
    const float* __restrict__ mr, float* __restrict__ outbh)
{
    __shared__ __align__(16) float As[16][128];
    __shared__ __align__(16) float Bs[16][64];
    const int bh = blockIdx.y;
    const int b = bh / HEADS, h = bh % HEADS;
    const int bm = blockIdx.x * 128;
    const float mean = mr[b * 2], rstd = mr[b * 2 + 1];
    float* Ab = attn + (size_t)bh * SEQ * SEQ;
    const float* Wb = lnw + (size_t)h * SEQ * SEQ;
    const float* Lb = lnb + (size_t)h * SEQ * SEQ;
    const float* Vb = v + (size_t)bh * SEQ * HD;
    const int tid = threadIdx.x;
    const int ty = tid >> 4, tx = tid & 15;

    float acc[8][4];
#pragma unroll
    for (int i = 0; i < 8; i++)
#pragma unroll
        for (int j = 0; j < 4; j++) acc[i][j] = 0.f;

    for (int kt = 0; kt < SEQ; kt += 16) {
#pragma unroll
        for (int l = 0; l < 2; l++) {
            int j = tid + l * 256;
            int row = j >> 2;
            int k4 = (j & 3) << 2;
            size_t off = (size_t)(bm + row) * SEQ + kt + k4;
            float4 va = *reinterpret_cast<const float4*>(&Ab[off]);
            float4 w  = *reinterpret_cast<const float4*>(&Wb[off]);
            float4 bb = *reinterpret_cast<const float4*>(&Lb[off]);
            va.x = (va.x - mean) * rstd * w.x + bb.x;
            va.y = (va.y - mean) * rstd * w.y + bb.y;
            va.z = (va.z - mean) * rstd * w.z + bb.z;
            va.w = (va.w - mean) * rstd * w.w + bb.w;
            *reinterpret_cast<float4*>(&Ab[off]) = va;   // normalized attn output
            As[k4 + 0][row] = va.x; As[k4 + 1][row] = va.y;
            As[k4 + 2][row] = va.z; As[k4 + 3][row] = va.w;
        }
        {
            int row = tid >> 4;              // k within tile
            int c4 = (tid & 15) << 2;        // d
            float4 vv = *reinterpret_cast<const float4*>(&Vb[(size_t)(kt + row) * HD + c4]);
            *reinterpret_cast<float4*>(&Bs[row][c4]) = vv;
        }
        __syncthreads();
#pragma unroll
        for (int k = 0; k < 16; k++) {
            float a[8], bv[4];
            *reinterpret_cast<float4*>(a)     = *reinterpret_cast<float4*>(&As[k][ty * 8]);
            *reinterpret_cast<float4*>(a + 4) = *reinterpret_cast<float4*>(&As[k][ty * 8 + 4]);
            *reinterpret_cast<float4*>(bv)    = *reinterpret_cast<float4*>(&Bs[k][tx * 4]);
#pragma unroll
            for (int i = 0; i < 8; i++)
#pragma unroll
                for (int j = 0; j < 4; j++) acc[i][j] = fmaf(a[i], bv[j], acc[i][j]);
        }
        __syncthreads();
    }
#pragma unroll
    for (int i = 0; i < 8; i++) {
        int n = bm + ty * 8 + i;
        float4 v0 = make_float4(acc[i][0], acc[i][1], acc[i][2], acc[i][3]);
        *reinterpret_cast<float4*>(&outbh[(size_t)(b * SEQ + n) * DIM + h * HD + tx * 4]) = v0;
    }
}

// -----------------------------------------------------------------------------
extern "C" void kernel_launch(void* const* d_in, const int* in_sizes, int n_in,
                              void* d_out, int out_size)
{
    const float* x      = (const float*)d_in[0];
    const float* qkv_w  = (const float*)d_in[1];
    const float* ln_w   = (const float*)d_in[2];
    const float* ln_b   = (const float*)d_in[3];
    const float* proj_w = (const float*)d_in[4];
    const float* proj_b = (const float*)d_in[5];

    float* outp  = (float*)d_out;                   // (B,N,DIM)
    float* attnp = outp + (size_t)MROWS * DIM;      // (B,H,N,N)

    float *p_qkv, *p_q2, *p_k2, *p_v, *p_outbh, *p_meanr;
    double* p_stats;
    cudaGetSymbolAddress((void**)&p_qkv, g_qkv);
    cudaGetSymbolAddress((void**)&p_q2, g_q2);
    cudaGetSymbolAddress((void**)&p_k2, g_k2);
    cudaGetSymbolAddress((void**)&p_v, g_v);
    cudaGetSymbolAddress((void**)&p_outbh, g_outbh);
    cudaGetSymbolAddress((void**)&p_stats, g_stats);
    cudaGetSymbolAddress((void**)&p_meanr, g_meanr);

    // 1) QKV = x @ qkv_w^T   (4096 x 2304 x 768)
    gemm_nt_kernel<<<dim3(QKV_COLS / 128, MROWS / 128), 256>>>(
        x, qkv_w, p_qkv, nullptr, MROWS, QKV_COLS, DIM);

    // 2) normalize + repack
    qkvnorm_kernel<<<BHN, 64>>>(p_qkv, p_q2, p_k2, p_v);

    // 3) stats zero + attn raw GEMM with fp64 stats accumulation
    zero_stats_kernel<<<1, 32>>>(p_stats);
    attn_gemm_kernel<<<dim3(SEQ / 128, SEQ / 128, BATCH * HEADS), 256>>>(
        p_q2, p_k2, attnp, p_stats);

    // 4) per-batch mean / rstd
    finalize_stats_kernel<<<1, 32>>>(p_stats, p_meanr);

    // 5) fused layernorm (writes normalized attn output) + attn @ v
    norm_attnv_kernel<<<dim3(SEQ / 128, BATCH * HEADS), 256>>>(
        attnp, ln_w, ln_b, p_v, p_meanr, p_outbh);

    // 6) out = outbh @ proj_w^T + proj_b   (4096 x 768 x 768)
    gemm_nt_kernel<<<dim3(DIM / 128, MROWS / 128), 256>>>(
        p_outbh, proj_w, outp, proj_b, MROWS, DIM, DIM);
}

// round 2
// speedup vs baseline: 2.1376x; 2.1376x over previous
#include <cuda_runtime.h>
#include <cuda_bf16.h>
#include <math.h>
#include <stdint.h>

#define BATCH 8
#define SEQ 512
#define DIM 768
#define HEADS 12
#define HD 64
#define MROWS (BATCH*SEQ)          // 4096
#define QKV_COLS (3*DIM)           // 2304
#define BH (BATCH*HEADS)           // 96
#define LN_EPS 1e-5f
#define LDS 24                     // padded smem row stride (elems) for 16-wide k-tiles

// ---------------- scratch (static device globals; no allocation) -------------
__device__ float g_qkv[MROWS * QKV_COLS];                 // 37.7 MB
__device__ __nv_bfloat16 g_xh[MROWS*DIM],  g_xl[MROWS*DIM];
__device__ __nv_bfloat16 g_qwh[QKV_COLS*DIM], g_qwl[QKV_COLS*DIM];
__device__ __nv_bfloat16 g_pwh[DIM*DIM],   g_pwl[DIM*DIM];
__device__ __nv_bfloat16 g_q2h[BH*SEQ*HD], g_q2l[BH*SEQ*HD];
__device__ __nv_bfloat16 g_k2h[BH*SEQ*HD], g_k2l[BH*SEQ*HD];
__device__ __nv_bfloat16 g_vh[BH*SEQ*HD],  g_vl[BH*SEQ*HD];
__device__ float g_outbh[MROWS*DIM];
__device__ __nv_bfloat16 g_oh[MROWS*DIM],  g_ol[MROWS*DIM];
__device__ double g_stats[16];
__device__ float g_meanr[16];

// ------------------------------- helpers -------------------------------------
__device__ __forceinline__ uint32_t cvta(const void* p) {
    return (uint32_t)__cvta_generic_to_shared(p);
}
__device__ __forceinline__ void mma16816(float* d, const uint32_t* a, const uint32_t* b) {
    asm volatile("mma.sync.aligned.m16n8k16.row.col.f32.bf16.bf16.f32 "
        "{%0,%1,%2,%3},{%4,%5,%6,%7},{%8,%9},{%0,%1,%2,%3};"
        : "+f"(d[0]), "+f"(d[1]), "+f"(d[2]), "+f"(d[3])
        : "r"(a[0]), "r"(a[1]), "r"(a[2]), "r"(a[3]), "r"(b[0]), "r"(b[1]));
}
__device__ __forceinline__ void ldsm4(uint32_t* r, uint32_t addr) {
    asm volatile("ldmatrix.sync.aligned.m8n8.x4.shared.b16 {%0,%1,%2,%3},[%4];"
        : "=r"(r[0]), "=r"(r[1]), "=r"(r[2]), "=r"(r[3]) : "r"(addr));
}
__device__ __forceinline__ void ldsm4t(uint32_t* r, uint32_t addr) {
    asm volatile("ldmatrix.sync.aligned.m8n8.x4.trans.shared.b16 {%0,%1,%2,%3},[%4];"
        : "=r"(r[0]), "=r"(r[1]), "=r"(r[2]), "=r"(r[3]) : "r"(addr));
}
__device__ __forceinline__ uint32_t pack2(__nv_bfloat16 a, __nv_bfloat16 b) {
    __nv_bfloat162 t = __halves2bfloat162(a, b);
    return *reinterpret_cast<uint32_t*>(&t);
}
// split 8 floats into hi/lo bf16 packs
__device__ __forceinline__ void split8(const float* f, uint4& uh, uint4& ul) {
    __nv_bfloat16 hb[8], lb[8];
#pragma unroll
    for (int i = 0; i < 8; i++) {
        hb[i] = __float2bfloat16(f[i]);
        lb[i] = __float2bfloat16(f[i] - __bfloat162float(hb[i]));
    }
    uh.x = pack2(hb[0], hb[1]); uh.y = pack2(hb[2], hb[3]);
    uh.z = pack2(hb[4], hb[5]); uh.w = pack2(hb[6], hb[7]);
    ul.x = pack2(lb[0], lb[1]); ul.y = pack2(lb[2], lb[3]);
    ul.z = pack2(lb[4], lb[5]); ul.w = pack2(lb[6], lb[7]);
}

// ------------------- split fp32 array into bf16 hi/lo ------------------------
__global__ __launch_bounds__(256) void split_kernel(
    const float* __restrict__ src, __nv_bfloat16* __restrict__ hi,
    __nv_bfloat16* __restrict__ lo, int n4)
{
    int i = blockIdx.x * 256 + threadIdx.x;
    if (i >= n4) return;
    float4 v = reinterpret_cast<const float4*>(src)[i];
    float f[4] = {v.x, v.y, v.z, v.w};
    __nv_bfloat16 h[4], l[4];
#pragma unroll
    for (int j = 0; j < 4; j++) {
        h[j] = __float2bfloat16(f[j]);
        l[j] = __float2bfloat16(f[j] - __bfloat162float(h[j]));
    }
    uint2 uh = make_uint2(pack2(h[0], h[1]), pack2(h[2], h[3]));
    uint2 ul = make_uint2(pack2(l[0], l[1]), pack2(l[2], l[3]));
    reinterpret_cast<uint2*>(hi)[i] = uh;
    reinterpret_cast<uint2*>(lo)[i] = ul;
}

// -------------- bf16x3 GEMM core: acc += A@B^T over K (block 128x128) --------
// 256 threads = 8 warps (4 m x 2 n), warp tile 32x64.
__device__ __forceinline__ void gemm3_core(
    const __nv_bfloat16* __restrict__ gAh, const __nv_bfloat16* __restrict__ gAl,
    const __nv_bfloat16* __restrict__ gBh, const __nv_bfloat16* __restrict__ gBl,
    int K, int bm, int bn,
    __nv_bfloat16* sAh, __nv_bfloat16* sAl, __nv_bfloat16* sBh, __nv_bfloat16* sBl,
    float acc[2][8][4])
{
    const int tid = threadIdx.x, lane = tid & 31, wid = tid >> 5;
    const int wm = (wid >> 1) * 32, wn = (wid & 1) * 64;
    const int lrow = tid >> 1, lhalf = tid & 1;
    const size_t aoff = (size_t)(bm + lrow) * K + lhalf * 8;
    const size_t boff = (size_t)(bn + lrow) * K + lhalf * 8;
    const int soff = lrow * LDS + lhalf * 8;
    const int SSTG = 128 * LDS;
    const int arow = lane & 15, akh = lane >> 4;
    const int brow = (lane & 7) + ((lane >> 4) << 3), bkh = (lane >> 3) & 1;

    uint4 rah = *(const uint4*)(gAh + aoff);
    uint4 ral = *(const uint4*)(gAl + aoff);
    uint4 rbh = *(const uint4*)(gBh + boff);
    uint4 rbl = *(const uint4*)(gBl + boff);

    for (int kt = 0, buf = 0; kt < K; kt += 16, buf ^= 1) {
        *(uint4*)(sAh + buf * SSTG + soff) = rah;
        *(uint4*)(sAl + buf * SSTG + soff) = ral;
        *(uint4*)(sBh + buf * SSTG + soff) = rbh;
        *(uint4*)(sBl + buf * SSTG + soff) = rbl;
        __syncthreads();
        if (kt + 16 < K) {
            rah = *(const uint4*)(gAh + aoff + kt + 16);
            ral = *(const uint4*)(gAl + aoff + kt + 16);
            rbh = *(const uint4*)(gBh + boff + kt + 16);
            rbl = *(const uint4*)(gBl + boff + kt + 16);
        }
        uint32_t ah[2][4], al_[2][4], bhf[4][4], blf[4][4];
#pragma unroll
        for (int mf = 0; mf < 2; mf++) {
            ldsm4(ah[mf],  cvta(sAh + buf * SSTG + (wm + mf * 16 + arow) * LDS + akh * 8));
            ldsm4(al_[mf], cvta(sAl + buf * SSTG + (wm + mf * 16 + arow) * LDS + akh * 8));
        }
#pragma unroll
        for (int nf4 = 0; nf4 < 4; nf4++) {
            ldsm4(bhf[nf4], cvta(sBh + buf * SSTG + (wn + nf4 * 16 + brow) * LDS + bkh * 8));
            ldsm4(blf[nf4], cvta(sBl + buf * SSTG + (wn + nf4 * 16 + brow) * LDS + bkh * 8));
        }
#pragma unroll
        for (int mf = 0; mf < 2; mf++)
#pragma unroll
            for (int nf = 0; nf < 8; nf++) {
                uint32_t* bH = &bhf[nf >> 1][(nf & 1) * 2];
                uint32_t* bL = &blf[nf >> 1][(nf & 1) * 2];
                mma16816(acc[mf][nf], ah[mf],  bH);
                mma16816(acc[mf][nf], ah[mf],  bL);
                mma16816(acc[mf][nf], al_[mf], bH);
            }
    }
}

// ------------- generic NT bf16x3 GEMM kernel: C = A@B^T (+bias) --------------
__global__ __launch_bounds__(256) void gemm3_nt(
    const __nv_bfloat16* __restrict__ Ah, const __nv_bfloat16* __restrict__ Al,
    const __nv_bfloat16* __restrict__ Bh, const __nv_bfloat16* __restrict__ Bl,
    float* __restrict__ C, const float* __restrict__ bias, int M, int N, int K)
{
    __shared__ __align__(16) __nv_bfloat16 sAh[2][128 * LDS], sAl[2][128 * LDS];
    __shared__ __align__(16) __nv_bfloat16 sBh[2][128 * LDS], sBl[2][128 * LDS];
    const int bm = blockIdx.y * 128, bn = blockIdx.x * 128;
    float acc[2][8][4];
#pragma unroll
    for (int i = 0; i < 2; i++)
#pragma unroll
        for (int j = 0; j < 8; j++)
#pragma unroll
            for (int k = 0; k < 4; k++) acc[i][j][k] = 0.f;

    gemm3_core(Ah, Al, Bh, Bl, K, bm, bn,
               &sAh[0][0], &sAl[0][0], &sBh[0][0], &sBl[0][0], acc);

    const int tid = threadIdx.x, lane = tid & 31, wid = tid >> 5;
    const int wm = (wid >> 1) * 32, wn = (wid & 1) * 64;
    const int rr = lane >> 2, cc = (lane & 3) * 2;
#pragma unroll
    for (int mf = 0; mf < 2; mf++) {
        int row0 = bm + wm + mf * 16 + rr;
#pragma unroll
        for (int nf = 0; nf < 8; nf++) {
            int col = bn + wn + nf * 8 + cc;
            float b0 = bias ? bias[col] : 0.f;
            float b1 = bias ? bias[col + 1] : 0.f;
            *(float2*)&C[(size_t)row0 * N + col] =
                make_float2(acc[mf][nf][0] + b0, acc[mf][nf][1] + b1);
            *(float2*)&C[(size_t)(row0 + 8) * N + col] =
                make_float2(acc[mf][nf][2] + b0, acc[mf][nf][3] + b1);
        }
    }
}

// --------- normalize q,k (squared-unit) + split to bf16 hi/lo; v split -------
__global__ __launch_bounds__(64) void qkvnorm_kernel(
    const float* __restrict__ qkv,
    __nv_bfloat16* __restrict__ q2h, __nv_bfloat16* __restrict__ q2l,
    __nv_bfloat16* __restrict__ k2h, __nv_bfloat16* __restrict__ k2l,
    __nv_bfloat16* __restrict__ vh,  __nv_bfloat16* __restrict__ vl)
{
    int idx = blockIdx.x;                 // b*H*SEQ + h*SEQ + n
    int n = idx & (SEQ - 1);
    int h = (idx / SEQ) % HEADS;
    int b = idx / (SEQ * HEADS);
    int lane = threadIdx.x & 31, w = threadIdx.x >> 5;

    const float* row = qkv + (size_t)(b * SEQ + n) * QKV_COLS;
    const float* src = row + w * DIM + h * HD;   // w=0:q, w=1:k
    float x0 = src[lane], x1 = src[lane + 32];
    float ss = x0 * x0 + x1 * x1;
#pragma unroll
    for (int o = 16; o; o >>= 1) ss += __shfl_xor_sync(0xffffffffu, ss, o);
    float inv = 1.0f / ss;
    float y0 = x0 * x0 * inv, y1 = x1 * x1 * inv;

    size_t base = ((size_t)(b * HEADS + h) * SEQ + n) * HD;
    __nv_bfloat16* dh = (w == 0 ? q2h : k2h) + base;
    __nv_bfloat16* dl = (w == 0 ? q2l : k2l) + base;
    __nv_bfloat16 h0 = __float2bfloat16(y0);
    __nv_bfloat16 h1 = __float2bfloat16(y1);
    dh[lane] = h0; dh[lane + 32] = h1;
    dl[lane]      = __float2bfloat16(y0 - __bfloat162float(h0));
    dl[lane + 32] = __float2bfloat16(y1 - __bfloat162float(h1));

    if (w == 0) {
        const float* vs = row + 2 * DIM + h * HD;
        float v0 = vs[lane], v1 = vs[lane + 32];
        __nv_bfloat16 vh0 = __float2bfloat16(v0);
        __nv_bfloat16 vh1 = __float2bfloat16(v1);
        vh[base + lane] = vh0; vh[base + lane + 32] = vh1;
        vl[base + lane]      = __float2bfloat16(v0 - __bfloat162float(vh0));
        vl[base + lane + 32] = __float2bfloat16(v1 - __bfloat162float(vh1));
    }
}

__global__ void zero_stats_kernel(double* s) { if (threadIdx.x < 16) s[threadIdx.x] = 0.0; }

// ---- attn_raw = q2 @ k2^T per (b,h) via bf16x3 mma; fp32 stats epilogue -----
__global__ __launch_bounds__(256) void attn3_kernel(
    const __nv_bfloat16* __restrict__ q2h, const __nv_bfloat16* __restrict__ q2l,
    const __nv_bfloat16* __restrict__ k2h, const __nv_bfloat16* __restrict__ k2l,
    float* __restrict__ attn, double* __restrict__ stats)
{
    __shared__ __align__(16) __nv_bfloat16 sAh[2][128 * LDS], sAl[2][128 * LDS];
    __shared__ __align__(16) __nv_bfloat16 sBh[2][128 * LDS], sBl[2][128 * LDS];
    const int bhz = blockIdx.z, b = bhz / HEADS;
    const size_t obase = (size_t)bhz * SEQ * HD;
    float* Cp = attn + (size_t)bhz * SEQ * SEQ;
    const int bm = blockIdx.y * 128, bn = blockIdx.x * 128;

    float acc[2][8][4];
#pragma unroll
    for (int i = 0; i < 2; i++)
#pragma unroll
        for (int j = 0; j < 8; j++)
#pragma unroll
            for (int k = 0; k < 4; k++) acc[i][j][k] = 0.f;

    gemm3_core(q2h + obase, q2l + obase, k2h + obase, k2l + obase, HD, bm, bn,
               &sAh[0][0], &sAl[0][0], &sBh[0][0], &sBl[0][0], acc);

    const int tid = threadIdx.x, lane = tid & 31, wid = tid >> 5;
    const int wm = (wid >> 1) * 32, wn = (wid & 1) * 64;
    const int rr = lane >> 2, cc = (lane & 3) * 2;
    float s1 = 0.f, s2 = 0.f;
#pragma unroll
    for (int mf = 0; mf < 2; mf++) {
        int row0 = bm + wm + mf * 16 + rr;
#pragma unroll
        for (int nf = 0; nf < 8; nf++) {
            int col = bn + wn + nf * 8 + cc;
            float v0 = acc[mf][nf][0], v1 = acc[mf][nf][1];
            float v2 = acc[mf][nf][2], v3 = acc[mf][nf][3];
            *(float2*)&Cp[(size_t)row0 * SEQ + col]       = make_float2(v0, v1);
            *(float2*)&Cp[(size_t)(row0 + 8) * SEQ + col] = make_float2(v2, v3);
            s1 += v0 + v1 + v2 + v3;
            s2 += v0 * v0 + v1 * v1 + v2 * v2 + v3 * v3;
        }
    }
#pragma unroll
    for (int o = 16; o; o >>= 1) {
        s1 += __shfl_xor_sync(0xffffffffu, s1, o);
        s2 += __shfl_xor_sync(0xffffffffu, s2, o);
    }
    __syncthreads();                        // tiles no longer needed
    float* red = reinterpret_cast<float*>(&sAh[0][0]);
    if (lane == 0) { red[wid] = s1; red[8 + wid] = s2; }
    __syncthreads();
    if (tid == 0) {
        float t1 = 0.f, t2 = 0.f;
#pragma unroll
        for (int i = 0; i < 8; i++) { t1 += red[i]; t2 += red[8 + i]; }
        atomicAdd(&stats[b * 2],     (double)t1);
        atomicAdd(&stats[b * 2 + 1], (double)t2);
    }
}

__global__ void finalize_stats_kernel(const double* __restrict__ s, float* __restrict__ mr)
{
    int b = threadIdx.x;
    if (b < BATCH) {
        double cnt = (double)HEADS * SEQ * SEQ;
        double mean = s[b * 2] / cnt;
        double var = s[b * 2 + 1] / cnt - mean * mean;
        mr[b * 2] = (float)mean;
        mr[b * 2 + 1] = (float)(1.0 / sqrt(var + (double)LN_EPS));
    }
}

// ---- fused: LN-normalize attn (writes 2nd output) + out = attn_n @ v --------
// per (b,h): C(128-row tile x 64), K=512; 8 warps of m16; bf16x3 mma
__global__ __launch_bounds__(256) void av_kernel(
    float* __restrict__ attn, const float* __restrict__ lnw,
    const float* __restrict__ lnb,
    const __nv_bfloat16* __restrict__ vh, const __nv_bfloat16* __restrict__ vl,
    const float* __restrict__ mr, float* __restrict__ outbh)
{
    __shared__ __align__(16) __nv_bfloat16 sAh[128 * LDS], sAl[128 * LDS];
    __shared__ __align__(16) __nv_bfloat16 sVh[16 * 72],  sVl[16 * 72];
    const int bhz = blockIdx.y;
    const int b = bhz / HEADS, h = bhz % HEADS;
    const int bm = blockIdx.x * 128;
    const float mean = mr[b * 2], rstd = mr[b * 2 + 1];
    float* Ab = attn + (size_t)bhz * SEQ * SEQ;
    const float* Wb = lnw + (size_t)h * SEQ * SEQ;
    const float* Lb = lnb + (size_t)h * SEQ * SEQ;
    const __nv_bfloat16* Vh = vh + (size_t)bhz * SEQ * HD;
    const __nv_bfloat16* Vl = vl + (size_t)bhz * SEQ * HD;

    const int tid = threadIdx.x, lane = tid & 31, wid = tid >> 5;
    const int lrow = tid >> 1, lhalf = tid & 1;
    const int arow = lane & 15, akh = lane >> 4;
    const int vkrow = (lane & 7) + ((lane >> 3) & 1) * 8;
    const int vnc = lane >> 4;

    float acc[8][4];
#pragma unroll
    for (int j = 0; j < 8; j++)
#pragma unroll
        for (int k = 0; k < 4; k++) acc[j][k] = 0.f;

    for (int kt = 0; kt < SEQ; kt += 16) {
        // ---- A: load raw attn + ln params, normalize, write back, split -----
        size_t off = (size_t)(bm + lrow) * SEQ + kt + lhalf * 8;
        float4 a0 = *(const float4*)&Ab[off],     a1 = *(const float4*)&Ab[off + 4];
        float4 w0 = *(const float4*)&Wb[off],     w1 = *(const float4*)&Wb[off + 4];
        float4 c0 = *(const float4*)&Lb[off],     c1 = *(const float4*)&Lb[off + 4];
        float f[8];
        f[0] = (a0.x - mean) * rstd * w0.x + c0.x;
        f[1] = (a0.y - mean) * rstd * w0.y + c0.y;
        f[2] = (a0.z - mean) * rstd * w0.z + c0.z;
        f[3] = (a0.w - mean) * rstd * w0.w + c0.w;
        f[4] = (a1.x - mean) * rstd * w1.x + c1.x;
        f[5] = (a1.y - mean) * rstd * w1.y + c1.y;
        f[6] = (a1.z - mean) * rstd * w1.z + c1.z;
        f[7] = (a1.w - mean) * rstd * w1.w + c1.w;
        *(float4*)&Ab[off]     = make_float4(f[0], f[1], f[2], f[3]);
        *(float4*)&Ab[off + 4] = make_float4(f[4], f[5], f[6], f[7]);
        uint4 uh, ul;
        split8(f, uh, ul);
        *(uint4*)&sAh[lrow * LDS + lhalf * 8] = uh;
        *(uint4*)&sAl[lrow * LDS + lhalf * 8] = ul;
        // ---- V tile (16 x 64) -----------------------------------------------
        if (tid < 128) {
            int vr = tid >> 3, vc = tid & 7;
            *(uint4*)&sVh[vr * 72 + vc * 8] =
                *(const uint4*)&Vh[(size_t)(kt + vr) * HD + vc * 8];
            *(uint4*)&sVl[vr * 72 + vc * 8] =
                *(const uint4*)&Vl[(size_t)(kt + vr) * HD + vc * 8];
        }
        __syncthreads();
        // ---- fragments -------------------------------------------------------
        uint32_t ah[4], al_[4], bhf[4][4], blf[4][4];
        ldsm4(ah,  cvta(&sAh[(wid * 16 + arow) * LDS + akh * 8]));
        ldsm4(al_, cvta(&sAl[(wid * 16 + arow) * LDS + akh * 8]));
#pragma unroll
        for (int nf4 = 0; nf4 < 4; nf4++) {
            ldsm4t(bhf[nf4], cvta(&sVh[vkrow * 72 + (nf4 * 2 + vnc) * 8]));
            ldsm4t(blf[nf4], cvta(&sVl[vkrow * 72 + (nf4 * 2 + vnc) * 8]));
        }
#pragma unroll
        for (int nf = 0; nf < 8; nf++) {
            uint32_t* bH = &bhf[nf >> 1][(nf & 1) * 2];
            uint32_t* bL = &blf[nf >> 1][(nf & 1) * 2];
            mma16816(acc[nf], ah,  bH);
            mma16816(acc[nf], ah,  bL);
            mma16816(acc[nf], al_, bH);
        }
        __syncthreads();
    }
    // epilogue: write (B,N,DIM) pre-proj activations
    const int rr = lane >> 2, cc = (lane & 3) * 2;
    int n0 = bm + wid * 16 + rr;
#pragma unroll
    for (int nf = 0; nf < 8; nf++) {
        int col = h * HD + nf * 8 + cc;
        *(float2*)&outbh[(size_t)(b * SEQ + n0) * DIM + col] =
            make_float2(acc[nf][0], acc[nf][1]);
        *(float2*)&outbh[(size_t)(b * SEQ + n0 + 8) * DIM + col] =
            make_float2(acc[nf][2], acc[nf][3]);
    }
}

// -----------------------------------------------------------------------------
extern "C" void kernel_launch(void* const* d_in, const int* in_sizes, int n_in,
                              void* d_out, int out_size)
{
    const float* x      = (const float*)d_in[0];
    const float* qkv_w  = (const float*)d_in[1];
    const float* ln_w   = (const float*)d_in[2];
    const float* ln_b   = (const float*)d_in[3];
    const float* proj_w = (const float*)d_in[4];
    const float* proj_b = (const float*)d_in[5];

    float* outp  = (float*)d_out;                   // (B,N,DIM)
    float* attnp = outp + (size_t)MROWS * DIM;      // (B,H,N,N)

    float *p_qkv, *p_outbh, *p_meanr;
    double* p_stats;
    __nv_bfloat16 *p_xh, *p_xl, *p_qwh, *p_qwl, *p_pwh, *p_pwl;
    __nv_bfloat16 *p_q2h, *p_q2l, *p_k2h, *p_k2l, *p_vh, *p_vl, *p_oh, *p_ol;
    cudaGetSymbolAddress((void**)&p_qkv, g_qkv);
    cudaGetSymbolAddress((void**)&p_xh, g_xh);   cudaGetSymbolAddress((void**)&p_xl, g_xl);
    cudaGetSymbolAddress((void**)&p_qwh, g_qwh); cudaGetSymbolAddress((void**)&p_qwl, g_qwl);
    cudaGetSymbolAddress((void**)&p_pwh, g_pwh); cudaGetSymbolAddress((void**)&p_pwl, g_pwl);
    cudaGetSymbolAddress((void**)&p_q2h, g_q2h); cudaGetSymbolAddress((void**)&p_q2l, g_q2l);
    cudaGetSymbolAddress((void**)&p_k2h, g_k2h); cudaGetSymbolAddress((void**)&p_k2l, g_k2l);
    cudaGetSymbolAddress((void**)&p_vh, g_vh);   cudaGetSymbolAddress((void**)&p_vl, g_vl);
    cudaGetSymbolAddress((void**)&p_outbh, g_outbh);
    cudaGetSymbolAddress((void**)&p_oh, g_oh);   cudaGetSymbolAddress((void**)&p_ol, g_ol);
    cudaGetSymbolAddress((void**)&p_stats, g_stats);
    cudaGetSymbolAddress((void**)&p_meanr, g_meanr);

    // splits for GEMM operands
    split_kernel<<<(MROWS*DIM/4 + 255)/256, 256>>>(x, p_xh, p_xl, MROWS*DIM/4);
    split_kernel<<<(QKV_COLS*DIM/4 + 255)/256, 256>>>(qkv_w, p_qwh, p_qwl, QKV_COLS*DIM/4);
    split_kernel<<<(DIM*DIM/4 + 255)/256, 256>>>(proj_w, p_pwh, p_pwl, DIM*DIM/4);

    // 1) QKV = x @ qkv_w^T   (4096 x 2304 x 768)
    gemm3_nt<<<dim3(QKV_COLS/128, MROWS/128), 256>>>(
        p_xh, p_xl, p_qwh, p_qwl, p_qkv, nullptr, MROWS, QKV_COLS, DIM);

    // 2) normalize + split/repack
    qkvnorm_kernel<<<BH*SEQ, 64>>>(p_qkv, p_q2h, p_q2l, p_k2h, p_k2l, p_vh, p_vl);

    // 3) attn raw GEMM + LN stats
    zero_stats_kernel<<<1, 32>>>(p_stats);
    attn3_kernel<<<dim3(SEQ/128, SEQ/128, BH), 256>>>(
        p_q2h, p_q2l, p_k2h, p_k2l, attnp, p_stats);

    // 4) per-batch mean / rstd
    finalize_stats_kernel<<<1, 32>>>(p_stats, p_meanr);

    // 5) fused layernorm (writes normalized attn output) + attn @ v
    av_kernel<<<dim3(SEQ/128, BH), 256>>>(
        attnp, ln_w, ln_b, p_vh, p_vl, p_meanr, p_outbh);

    // 6) out = outbh @ proj_w^T + proj_b   (4096 x 768 x 768)
    split_kernel<<<(MROWS*DIM/4 + 255)/256, 256>>>(p_outbh, p_oh, p_ol, MROWS*DIM/4);
    gemm3_nt<<<dim3(DIM/128, MROWS/128), 256>>>(
        p_oh, p_ol, p_pwh, p_pwl, outp, proj_b, MROWS, DIM, DIM);
}